// round 5
// baseline (speedup 1.0000x reference)
#include <cuda_runtime.h>
#include <cuda_bf16.h>
#include <cstdint>

#define TT 512
#define CC 64
#define NB 1024  // B*T

// scratch (allocation-free rule: __device__ globals)
__device__ float g_kp[NB * CC];
__device__ float g_qp[NB * CC];        // qp + b1 folded
__device__ float g_v [NB * CC];
__device__ float g_logits[NB * TT];    // partial logits
__device__ __nv_bfloat16 g_Wt[64 * 128];  // W1p^T bf16, [n][k]
__device__ int g_cnt[NB];              // chunk-completion counters (self-resetting)

// ---------------- kernel 1: projections + W1p transpose ----------------
// blocks 0..255: 4 tokens each, weights read directly (L1). 256..263: g_Wt fill.
__global__ __launch_bounds__(256) void prep_kernel(
    const float* __restrict__ x, const float* __restrict__ pos,
    const float* __restrict__ W1, const float* __restrict__ b1,
    const float* __restrict__ Wv, const float* __restrict__ bv)
{
    const int tid = threadIdx.x;

    if (blockIdx.x >= 256) {
        int base = (blockIdx.x - 256) * 1024 + tid;
#pragma unroll
        for (int r = 0; r < 4; r++) {
            int idx = base + r * 256;       // 0..8191
            int n = idx >> 7, k = idx & 127;
            g_Wt[n * 128 + k] = __float2bfloat16_rn(W1[(128 + k) * 64 + n]);
        }
        return;
    }

    __shared__ float xs[256], x1s[256];
    const int t0 = blockIdx.x * 4;
    const int tl = tid >> 6;
    const int c  = tid & 63;
    {
        float xv = x[(t0 + tl) * 64 + c];
        xs [tid] = xv;
        x1s[tid] = xv + pos[(((t0 + tl) & (TT - 1)) * 64) + c];
    }
    __syncthreads();

    const int bi = t0 + tl;
    float ak = 0.f, aq = 0.f, av = 0.f;
#pragma unroll 8
    for (int k = 0; k < 64; k++) {
        float x1v = x1s[tl * 64 + k];
        float xv  = xs [tl * 64 + k];
        ak = fmaf(x1v, W1[k * 64 + c], ak);
        aq = fmaf(x1v, W1[(64 + k) * 64 + c], aq);
        av = fmaf(xv,  Wv[k * 64 + c], av);
    }
    g_kp[bi * 64 + c] = ak;
    g_qp[bi * 64 + c] = aq + b1[c];
    g_v [bi * 64 + c] = av + bv[c];
}

// ---------------- kernel 2: (b, i, chunk) blocks + fused softmax/AV ----------------
// smem bytes: As[128][136]bf16 34816@0, Wt[64][136]bf16 17408@34816,
//             qp_s 256@52224, W2_s 256@52480
// winner-phase reuse of As region: logits 2048@0, red 1024@2048, rbuf 32@3072, flag@3104
#define SMEM_BYTES 52736
#define NCHUNK_BLKS 1280

__global__ __launch_bounds__(256, 4) void attn_kernel(
    const float* __restrict__ pdist,
    const float* __restrict__ W2,
    const float* __restrict__ b2,
    float* __restrict__ out)
{
    extern __shared__ char smem[];
    __nv_bfloat16* As = (__nv_bfloat16*)(smem);
    __nv_bfloat16* Wt = (__nv_bfloat16*)(smem + 34816);
    float* qp_s = (float*)(smem + 52224);
    float* W2_s = (float*)(smem + 52480);
    // winner-phase aliases (As region, used only after all MMA/epilogue done)
    float* ls    = (float*)(smem);
    float* red   = (float*)(smem + 2048);
    float* rbuf  = (float*)(smem + 3072);
    int*   sflag = (int*)(smem + 3104);

    const int tid = threadIdx.x;

    // decode (b, i, ch)
    int z = blockIdx.x;
    int b = 0;
    if (z >= NCHUNK_BLKS) { b = 1; z -= NCHUNK_BLKS; }
    int ch, i;
    if (z < 512)       { ch = 0; i = z; }
    else if (z < 896)  { ch = 1; i = 128 + (z - 512); }
    else if (z < 1152) { ch = 2; i = 256 + (z - 896); }
    else               { ch = 3; i = 384 + (z - 1152); }
    const int bi    = b * TT + i;
    const int jbase = ch << 7;
    const int imax  = i - jbase;
    const int nch   = (i >> 7) + 1;

    // ---- Wt fill from precomputed g_Wt (coalesced 16B copies) ----
#pragma unroll
    for (int r = 0; r < 4; r++) {
        int s = tid + r * 256;
        int n = s >> 4, k8 = s & 15;
        uint4 u = *(const uint4*)((const char*)g_Wt + n * 256 + k8 * 16);
        *(uint4*)((char*)Wt + n * 272 + k8 * 16) = u;
    }
    if (tid < 64) {
        qp_s[tid] = g_qp[bi * 64 + tid];
        W2_s[tid] = W2[tid];
    }
    __syncthreads();

    const int lane = tid & 31;
    const int w    = tid >> 5;
    const int g    = lane >> 2;
    const int tc   = lane & 3;
    const int wrow = w * 16;

    if (wrow <= imax) {
        const int rmaxi = imax - wrow;

        // per-warp load of its own 16 rows (fp32 -> bf16, padded)
        const float4* src = (const float4*)(pdist + ((size_t)bi * TT + jbase) * 128);
#pragma unroll
        for (int r = 0; r < 16; r++) {
            if (r <= rmaxi) {
                int jloc = wrow + r;
                float4 vv = src[jloc * 32 + lane];
                __nv_bfloat162 lo = __floats2bfloat162_rn(vv.x, vv.y);
                __nv_bfloat162 hi = __floats2bfloat162_rn(vv.z, vv.w);
                uint2 u;
                u.x = *(uint32_t*)&lo;
                u.y = *(uint32_t*)&hi;
                *(uint2*)((char*)As + jloc * 272 + lane * 8) = u;
            }
        }
        __syncwarp();

        uint32_t As_u = (uint32_t)__cvta_generic_to_shared(As);
        uint32_t Wt_u = (uint32_t)__cvta_generic_to_shared(Wt);
        uint32_t a_base = As_u + (uint32_t)((wrow + (lane & 7) + ((lane >> 3) & 1) * 8) * 272
                                            + (lane >> 4) * 16);
        const int nrow  = (lane & 7) + ((lane >> 4) << 3);
        const int khalf = ((lane >> 3) & 1) * 8;
        uint32_t b_base = Wt_u + (uint32_t)((nrow * 136 + khalf) * 2);

        float acc[32];
#pragma unroll
        for (int zz = 0; zz < 32; zz++) acc[zz] = 0.f;

#pragma unroll
        for (int kt = 0; kt < 8; kt++) {
            uint32_t a0, a1, a2, a3;
            asm volatile("ldmatrix.sync.aligned.m8n8.x4.shared.b16 {%0,%1,%2,%3}, [%4];"
                         : "=r"(a0), "=r"(a1), "=r"(a2), "=r"(a3)
                         : "r"(a_base + kt * 32));
#pragma unroll
            for (int nt2 = 0; nt2 < 4; nt2++) {
                uint32_t r0, r1, r2, r3;
                asm volatile("ldmatrix.sync.aligned.m8n8.x4.shared.b16 {%0,%1,%2,%3}, [%4];"
                             : "=r"(r0), "=r"(r1), "=r"(r2), "=r"(r3)
                             : "r"(b_base + (uint32_t)(nt2 * 16 * 272 + kt * 32)));
                int nt = nt2 * 2;
                asm volatile(
                    "mma.sync.aligned.m16n8k16.row.col.f32.bf16.bf16.f32 "
                    "{%0,%1,%2,%3}, {%4,%5,%6,%7}, {%8,%9}, {%0,%1,%2,%3};"
                    : "+f"(acc[nt * 4 + 0]), "+f"(acc[nt * 4 + 1]),
                      "+f"(acc[nt * 4 + 2]), "+f"(acc[nt * 4 + 3])
                    : "r"(a0), "r"(a1), "r"(a2), "r"(a3), "r"(r0), "r"(r1));
                asm volatile(
                    "mma.sync.aligned.m16n8k16.row.col.f32.bf16.bf16.f32 "
                    "{%0,%1,%2,%3}, {%4,%5,%6,%7}, {%8,%9}, {%0,%1,%2,%3};"
                    : "+f"(acc[nt * 4 + 4]), "+f"(acc[nt * 4 + 5]),
                      "+f"(acc[nt * 4 + 6]), "+f"(acc[nt * 4 + 7])
                    : "r"(a0), "r"(a1), "r"(a2), "r"(a3), "r"(r2), "r"(r3));
            }
        }

        // fused epilogue: +qp'+kp, gelu (tanh form, MUFU), dot W2
        {
            const int j0 = jbase + wrow + g;
            const int j1 = j0 + 8;
            const float* kp0 = g_kp + ((size_t)b * TT + j0) * 64;
            const float* kp1 = kp0 + 8 * 64;
            float p0 = 0.f, p1 = 0.f;
#pragma unroll
            for (int nt = 0; nt < 8; nt++) {
                int c = nt * 8 + 2 * tc;
                float2 k0 = *(const float2*)(kp0 + c);
                float2 k1 = *(const float2*)(kp1 + c);
                float q0 = qp_s[c], q1 = qp_s[c + 1];
                float w20 = W2_s[c], w21 = W2_s[c + 1];
                float hh, h2, e, gg;
                hh = acc[nt * 4 + 0] + q0 + k0.x;
                h2 = hh * hh;
                e  = __expf(hh * fmaf(0.07135481628f, h2, 1.5957691216f));
                gg = hh - __fdividef(hh, e + 1.f);
                p0 = fmaf(w20, gg, p0);
                hh = acc[nt * 4 + 1] + q1 + k0.y;
                h2 = hh * hh;
                e  = __expf(hh * fmaf(0.07135481628f, h2, 1.5957691216f));
                gg = hh - __fdividef(hh, e + 1.f);
                p0 = fmaf(w21, gg, p0);
                hh = acc[nt * 4 + 2] + q0 + k1.x;
                h2 = hh * hh;
                e  = __expf(hh * fmaf(0.07135481628f, h2, 1.5957691216f));
                gg = hh - __fdividef(hh, e + 1.f);
                p1 = fmaf(w20, gg, p1);
                hh = acc[nt * 4 + 3] + q1 + k1.y;
                h2 = hh * hh;
                e  = __expf(hh * fmaf(0.07135481628f, h2, 1.5957691216f));
                gg = hh - __fdividef(hh, e + 1.f);
                p1 = fmaf(w21, gg, p1);
            }
            p0 += __shfl_xor_sync(0xffffffffu, p0, 1);
            p0 += __shfl_xor_sync(0xffffffffu, p0, 2);
            p1 += __shfl_xor_sync(0xffffffffu, p1, 1);
            p1 += __shfl_xor_sync(0xffffffffu, p1, 2);
            if (tc == 0) {
                g_logits[bi * TT + j0] = p0;
                g_logits[bi * TT + j1] = p1;
            }
        }
    }

    // ---- last-chunk-block does softmax + AV for this row ----
    __syncthreads();
    if (tid == 0) {
        __threadfence();
        int old = atomicAdd(&g_cnt[bi], 1);
        if (old == nch - 1) {
            *sflag = 1;
            g_cnt[bi] = 0;   // self-reset for next launch/replay
        } else {
            *sflag = 0;
        }
    }
    __syncthreads();
    if (!*sflag) return;
    __threadfence();  // acquire: other blocks' logits now in L2

    const float b2v = b2[0];
    float lmax = -1e30f;
    for (int j = tid; j <= i; j += 256) {
        float l = (__ldcg(&g_logits[bi * TT + j]) + b2v) * 0.125f;
        ls[j] = l;
        lmax = fmaxf(lmax, l);
    }
#pragma unroll
    for (int o = 16; o; o >>= 1) lmax = fmaxf(lmax, __shfl_xor_sync(0xffffffffu, lmax, o));
    if (lane == 0) rbuf[w] = lmax;
    __syncthreads();
    float gmax = rbuf[0];
#pragma unroll
    for (int zz = 1; zz < 8; zz++) gmax = fmaxf(gmax, rbuf[zz]);
    __syncthreads();

    float lsum = 0.f;
    for (int j = tid; j <= i; j += 256) {
        float p = __expf(ls[j] - gmax);
        ls[j] = p;
        lsum += p;
    }
#pragma unroll
    for (int o = 16; o; o >>= 1) lsum += __shfl_xor_sync(0xffffffffu, lsum, o);
    if (lane == 0) rbuf[w] = lsum;
    __syncthreads();
    float tot = rbuf[0];
#pragma unroll
    for (int zz = 1; zz < 8; zz++) tot += rbuf[zz];
    const float inv = 1.f / tot;
    __syncthreads();

    const int h = tid & 63, q = tid >> 6;
    const float* vb = g_v + (size_t)b * TT * 64;
    float a0 = 0.f;
#pragma unroll 4
    for (int j = q; j <= i; j += 4)
        a0 = fmaf(ls[j], vb[j * 64 + h], a0);
    red[q * 64 + h] = a0;
    __syncthreads();
    if (tid < 64) {
        float r = red[tid] + red[tid + 64] + red[tid + 128] + red[tid + 192];
        out[bi * 64 + tid] = r * inv;
    }
}

// ---------------- launcher ----------------
extern "C" void kernel_launch(void* const* d_in, const int* in_sizes, int n_in,
                              void* d_out, int out_size)
{
    const float* x     = (const float*)d_in[0];
    const float* pos   = (const float*)d_in[1];
    const float* pdist = (const float*)d_in[2];
    const float* W1    = (const float*)d_in[3];
    const float* b1    = (const float*)d_in[4];
    const float* W2    = (const float*)d_in[5];
    const float* b2    = (const float*)d_in[6];
    const float* Wv    = (const float*)d_in[7];
    const float* bv    = (const float*)d_in[8];
    float* out = (float*)d_out;

    cudaFuncSetAttribute(attn_kernel, cudaFuncAttributeMaxDynamicSharedMemorySize, SMEM_BYTES);

    prep_kernel<<<264, 256>>>(x, pos, W1, b1, Wv, bv);
    attn_kernel<<<2 * NCHUNK_BLKS, 256, SMEM_BYTES>>>(pdist, W2, b2, out);
}